// round 8
// baseline (speedup 1.0000x reference)
#include <cuda_runtime.h>
#include <math.h>

#define Bv  8
#define Tv  32
#define Nv  500
#define Fv  64
#define Hv  128
#define Ev  8000
#define BT  256            // B*T
#define BTN 128000         // B*T*N
#define NNZ (Ev + Nv)

// ---------------- scratch (static device globals: allowed) ----------------
__device__ float  g_xf [BTN * Hv];   // x @ W_gcn            (bt, n, h)
__device__ float  g_res[BTN * Hv];   // x @ W_res + b_res    (bt, n, h)
__device__ float  g_hg [BTN * Hv];   // gelu(gcn agg + b)    (bt, n, h)
__device__ float  g_wt [384 * Hv];   // W_temp transposed: [(i*3+k)][o]
__device__ float  g_deg [Nv];
__device__ float  g_dinv[Nv];
__device__ int    g_cnt [Nv];
__device__ int    g_rowptr[Nv + 1];
__device__ int    g_fill[Nv];
__device__ float2 g_ev[NNZ];         // {norm, __int_as_float(src)} CSR by dst
__device__ int    g_is64;            // edge_index dtype flag

// ---------------- helpers ----------------
__device__ __forceinline__ unsigned long long pack2(float lo, float hi) {
    unsigned long long r;
    asm("mov.b64 %0, {%1, %2};" : "=l"(r) : "f"(lo), "f"(hi));
    return r;
}
__device__ __forceinline__ void unpack2(unsigned long long v, float& lo, float& hi) {
    asm("mov.b64 {%0, %1}, %2;" : "=f"(lo), "=f"(hi) : "l"(v));
}
__device__ __forceinline__ void fma2(unsigned long long& d, unsigned long long a,
                                     unsigned long long b) {
    asm("fma.rn.f32x2 %0, %1, %2, %0;" : "+l"(d) : "l"(a), "l"(b));
}
__device__ __forceinline__ float gelu_exact(float x) {
    return 0.5f * x * (1.0f + erff(x * 0.7071067811865476f));
}
__device__ __forceinline__ int load_idx(const void* ei, int i) {
    long long v;
    if (g_is64) v = ((const long long*)ei)[i];
    else        v = ((const int*)ei)[i];
    if (v < 0) v = 0;
    if (v >= Nv) v = Nv - 1;
    return (int)v;
}

// ---------------- P0: dtype detect + zero counters (merged) --------------
__global__ void p_start(const void* __restrict__ ei) {
    int i = threadIdx.x;
    if (i == 0) {
        const long long* p = (const long long*)ei;
        int ok64 = 1;
        for (int j = 0; j < 8; ++j) {
            long long v = p[j];
            if (v < 0 || v >= Nv) ok64 = 0;
        }
        g_is64 = ok64;
    }
    if (i < Nv) { g_deg[i] = 0.0f; g_cnt[i] = 0; }
}

// ---------------- P1: degree + in-edge counts ----------------
__global__ void p_deg(const void* __restrict__ ei, const float* __restrict__ ew) {
    int e = blockIdx.x * blockDim.x + threadIdx.x;
    if (e >= Ev) return;
    int dst = load_idx(ei, Ev + e);
    atomicAdd(&g_deg[dst], ew[e]);
    atomicAdd(&g_cnt[dst], 1);
}

// ---------------- P2: dinv + prefix scan -> rowptr/fill ----------------
__global__ void p_scan() {
    __shared__ int s[512];
    int tid = threadIdx.x;
    int c = 0;
    if (tid < Nv) {
        float d = g_deg[tid] + 1.0f;           // + self loop weight
        g_dinv[tid] = 1.0f / sqrtf(d);
        c = g_cnt[tid] + 1;                    // + self loop edge
    }
    s[tid] = c;
    __syncthreads();
    for (int off = 1; off < 512; off <<= 1) {
        int v = (tid >= off) ? s[tid - off] : 0;
        __syncthreads();
        s[tid] += v;
        __syncthreads();
    }
    if (tid < Nv) {
        g_rowptr[tid + 1] = s[tid];
        g_fill[tid] = s[tid] - c;
        if (tid == 0) g_rowptr[0] = 0;
    }
}

// ---------------- P3: CSR fill with normalized edge values ----------------
__global__ void p_fill(const void* __restrict__ ei, const float* __restrict__ ew) {
    int e = blockIdx.x * blockDim.x + threadIdx.x;
    if (e >= NNZ) return;
    int src, dst; float w;
    if (e < Ev) { src = load_idx(ei, e); dst = load_idx(ei, Ev + e); w = ew[e]; }
    else        { src = dst = e - Ev; w = 1.0f; }
    float v = g_dinv[src] * w * g_dinv[dst];
    int pos = atomicAdd(&g_fill[dst], 1);
    if (pos >= 0 && pos < NNZ)
        g_ev[pos] = make_float2(v, __int_as_float(src));
}

// ---------------- P4: transpose W_temp -> [m=(i*3+k)][o] (coalesced conv) --
__global__ void p_wtrans(const float* __restrict__ Wt) {
    int idx = blockIdx.x * 256 + threadIdx.x;
    if (idx >= 128 * 384) return;
    int o = idx / 384, m = idx % 384;
    g_wt[m * Hv + o] = Wt[o * 384 + m];
}

// ---------------- K2: fused input projections (xf + res), f32x2 packed ----
__global__ __launch_bounds__(128) void k_inproj(
    const float* __restrict__ x, const float* __restrict__ Wg,
    const float* __restrict__ Wr, const float* __restrict__ br) {
    __shared__ float sx[8][64];
    int h = threadIdx.x;
    unsigned long long wp[64];
#pragma unroll
    for (int i = 0; i < 64; ++i) wp[i] = pack2(Wg[i * Hv + h], Wr[i * Hv + h]);
    float brh = br[h];
    int row0 = blockIdx.x * 128;
#pragma unroll 1
    for (int c = 0; c < 16; ++c) {
        int rbase = row0 + c * 8;
        __syncthreads();
        for (int j = h; j < 512; j += 128)
            sx[j >> 6][j & 63] = x[(rbase + (j >> 6)) * Fv + (j & 63)];
        __syncthreads();
#pragma unroll
        for (int r = 0; r < 8; ++r) {
            unsigned long long acc = 0ULL;
#pragma unroll
            for (int i = 0; i < 64; i += 4) {
                float4 xv = *(const float4*)&sx[r][i];
                fma2(acc, pack2(xv.x, xv.x), wp[i + 0]);
                fma2(acc, pack2(xv.y, xv.y), wp[i + 1]);
                fma2(acc, pack2(xv.z, xv.z), wp[i + 2]);
                fma2(acc, pack2(xv.w, xv.w), wp[i + 3]);
            }
            float ag, ar; unpack2(acc, ag, ar);
            int row = rbase + r;
            g_xf [row * Hv + h] = ag;
            g_res[row * Hv + h] = ar + brh;
        }
    }
}

// ---------------- K3: GCN aggregate + bias + gelu (32-ch tiles, f32x2) ----
// 32 h-channels per block, 2 per thread; smem 500*16*8 = 64000 B dynamic
__global__ __launch_bounds__(128) void k_gcn(const float* __restrict__ bg) {
    extern __shared__ __align__(16) float2 sxf2[];   // [500][16] float2
    int bt = blockIdx.x;
    int hbase = blockIdx.y * 32;
    int tid = threadIdx.x;
    const float2* xsrc2 = (const float2*)(g_xf + (size_t)bt * (Nv * Hv));
    int cbase2 = hbase >> 1;
    for (int idx = tid; idx < Nv * 16; idx += 128) {
        int n = idx >> 4, c2 = idx & 15;
        sxf2[idx] = xsrc2[n * 64 + cbase2 + c2];
    }
    __syncthreads();
    int hh2 = tid & 15;              // channel pair within tile
    int ns = tid >> 4;               // 0..7
    int ch = hbase + 2 * hh2;
    float bg0 = bg[ch], bg1 = bg[ch + 1];
    float2* dst2 = (float2*)(g_hg + (size_t)bt * (Nv * Hv));
    const unsigned long long* sxp = (const unsigned long long*)sxf2;
    for (int n = ns; n < Nv; n += 8) {
        int rs = g_rowptr[n], re = g_rowptr[n + 1];
        unsigned long long acc = 0ULL;
        int e = rs;
        for (; e + 1 < re; e += 2) {
            float2 ev0 = g_ev[e];
            float2 ev1 = g_ev[e + 1];
            fma2(acc, pack2(ev0.x, ev0.x), sxp[__float_as_int(ev0.y) * 16 + hh2]);
            fma2(acc, pack2(ev1.x, ev1.x), sxp[__float_as_int(ev1.y) * 16 + hh2]);
        }
        if (e < re) {
            float2 ev0 = g_ev[e];
            fma2(acc, pack2(ev0.x, ev0.x), sxp[__float_as_int(ev0.y) * 16 + hh2]);
        }
        float a0, a1; unpack2(acc, a0, a1);
        dst2[n * 64 + (ch >> 1)] =
            make_float2(gelu_exact(a0 + bg0), gelu_exact(a1 + bg1));
    }
}

// ---------------- K4: temporal conv(K=3) + gelu + residual + LayerNorm ----
// f32x2 accumulators; weights read coalesced from transposed g_wt.
__global__ __launch_bounds__(128) void k_conv(
    const float* __restrict__ btmp,
    const float* __restrict__ lnw, const float* __restrict__ lnb,
    float* __restrict__ out) {
    // input staged as [tt=34][i=128][g=2]  (tt = t_in + 1, rows 0 and 33 are pad)
    __shared__ __align__(16) float sh[34 * 256];
    __shared__ float smu[64], srs[64];
    int o = threadIdx.x;
    int p0 = blockIdx.x * 2;
    int b0 = p0 / Nv, n0 = p0 % Nv;
    int b1 = (p0 + 1) / Nv, n1 = (p0 + 1) % Nv;

    // load input tiles (channel o of both pairs, padded in t)
#pragma unroll
    for (int g = 0; g < 2; ++g) {
        int b = g ? b1 : b0, n = g ? n1 : n0;
        sh[0 * 256 + 2 * o + g] = 0.0f;
        sh[33 * 256 + 2 * o + g] = 0.0f;
        for (int t = 0; t < 32; ++t)
            sh[(t + 1) * 256 + 2 * o + g] = g_hg[((b * Tv + t) * Nv + n) * Hv + o];
    }
    __syncthreads();

    unsigned long long acc[32];
#pragma unroll
    for (int t = 0; t < 32; ++t) acc[t] = 0ULL;

    const float* wtp = g_wt + o;             // [(it*24+j)][o], lane-coalesced
    const unsigned long long* shp = (const unsigned long long*)sh; // [tt][i] pairs
#pragma unroll 1
    for (int it = 0; it < 16; ++it) {
        float w[24];
#pragma unroll
        for (int j = 0; j < 24; ++j) w[j] = wtp[(it * 24 + j) * Hv];
#pragma unroll
        for (int ii = 0; ii < 8; ++ii) {
            int i = it * 8 + ii;
            unsigned long long w0 = pack2(w[ii * 3 + 0], w[ii * 3 + 0]);
            unsigned long long w1 = pack2(w[ii * 3 + 1], w[ii * 3 + 1]);
            unsigned long long w2 = pack2(w[ii * 3 + 2], w[ii * 3 + 2]);
            const unsigned long long* col = shp + i;   // stride 128 per tt
            unsigned long long v0 = col[0];
            unsigned long long v1 = col[128];
#pragma unroll
            for (int t = 0; t < 32; ++t) {
                unsigned long long v2 = col[(t + 2) * 128];
                fma2(acc[t], w0, v0);
                fma2(acc[t], w1, v1);
                fma2(acc[t], w2, v2);
                v0 = v1; v1 = v2;
            }
        }
    }
    __syncthreads();   // done reading input; reuse sh as y buffer [64][129]

    float btv = btmp[o];
    float* shy = sh;
#pragma unroll
    for (int t = 0; t < 32; ++t) {
        float y0, y1; unpack2(acc[t], y0, y1);
        float h0 = gelu_exact(y0 + btv);
        float h1 = gelu_exact(y1 + btv);
        h0 += g_res[((b0 * Tv + t) * Nv + n0) * Hv + o];
        h1 += g_res[((b1 * Tv + t) * Nv + n1) * Hv + o];
        shy[t * 129 + o] = h0;
        shy[(32 + t) * 129 + o] = h1;
    }
    __syncthreads();

    if (o < 64) {
        int r = o;
        float s1 = 0.0f;
#pragma unroll 8
        for (int j = 0; j < 128; ++j) s1 += shy[r * 129 + j];
        float mu = s1 * (1.0f / 128.0f);
        float s2 = 0.0f;
#pragma unroll 8
        for (int j = 0; j < 128; ++j) {
            float d = shy[r * 129 + j] - mu;
            s2 += d * d;
        }
        smu[r] = mu;
        srs[r] = 1.0f / sqrtf(s2 * (1.0f / 128.0f) + 1e-5f);
    }
    __syncthreads();

    float lw = lnw[o], lb = lnb[o];
#pragma unroll
    for (int g = 0; g < 2; ++g) {
        int b = g ? b1 : b0, n = g ? n1 : n0;
        for (int t = 0; t < 32; ++t) {
            int r = g * 32 + t;
            float v = shy[r * 129 + o];
            out[((b * Tv + t) * Nv + n) * Hv + o] = (v - smu[r]) * srs[r] * lw + lb;
        }
    }
}

// ---------------- launch ----------------
extern "C" void kernel_launch(void* const* d_in, const int* in_sizes, int n_in,
                              void* d_out, int out_size) {
    const float* x   = (const float*)d_in[0];
    const void*  ei  = d_in[1];
    const float* ew  = (const float*)d_in[2];
    const float* Wg  = (const float*)d_in[3];
    const float* bg  = (const float*)d_in[4];
    const float* Wt  = (const float*)d_in[5];
    const float* btm = (const float*)d_in[6];
    const float* lnw = (const float*)d_in[7];
    const float* lnb = (const float*)d_in[8];
    const float* Wr  = (const float*)d_in[9];
    const float* br  = (const float*)d_in[10];
    float* out = (float*)d_out;

    cudaFuncSetAttribute(k_gcn, cudaFuncAttributeMaxDynamicSharedMemorySize, 64000);

    p_start<<<1, 512>>>(ei);
    p_deg <<<(Ev + 127) / 128, 128>>>(ei, ew);
    p_scan<<<1, 512>>>();
    p_fill<<<(NNZ + 127) / 128, 128>>>(ei, ew);
    p_wtrans<<<192, 256>>>(Wt);
    k_inproj<<<1000, 128>>>(x, Wg, Wr, br);
    k_gcn<<<dim3(BT, 4), 128, 64000>>>(bg);
    k_conv<<<2000, 128>>>(btm, lnw, lnb, out);
}

// round 9
// speedup vs baseline: 1.1805x; 1.1805x over previous
#include <cuda_runtime.h>
#include <math.h>

#define Bv  8
#define Tv  32
#define Nv  500
#define Fv  64
#define Hv  128
#define Ev  8000
#define BT  256            // B*T
#define BTN 128000         // B*T*N
#define NNZ (Ev + Nv)

// ---------------- scratch (static device globals: allowed) ----------------
__device__ float  g_xf [BTN * Hv];   // x @ W_gcn            (bt, n, h)
__device__ float  g_res[BTN * Hv];   // x @ W_res + b_res    (bt, n, h)
__device__ float  g_hg [BTN * Hv];   // gelu(gcn agg + b)    (bt, n, h)
__device__ float  g_wt [384 * Hv];   // W_temp transposed: [(i*3+k)][o]
__device__ int    g_rowptr[Nv + 1];
__device__ float2 g_ev[NNZ];         // {norm, __int_as_float(src)} CSR by dst

// ---------------- helpers ----------------
__device__ __forceinline__ unsigned long long pack2(float lo, float hi) {
    unsigned long long r;
    asm("mov.b64 %0, {%1, %2};" : "=l"(r) : "f"(lo), "f"(hi));
    return r;
}
__device__ __forceinline__ void unpack2(unsigned long long v, float& lo, float& hi) {
    asm("mov.b64 {%0, %1}, %2;" : "=f"(lo), "=f"(hi) : "l"(v));
}
__device__ __forceinline__ void fma2(unsigned long long& d, unsigned long long a,
                                     unsigned long long b) {
    asm("fma.rn.f32x2 %0, %1, %2, %0;" : "+l"(d) : "l"(a), "l"(b));
}
__device__ __forceinline__ float gelu_exact(float x) {
    return 0.5f * x * (1.0f + erff(x * 0.7071067811865476f));
}

// =============== P: one-kernel prep ===============
// block 0: dtype detect + degree + scan + CSR fill (all in smem)
// blocks 1..192: transpose W_temp -> g_wt
__global__ __launch_bounds__(256) void p_prep(
    const void* __restrict__ ei, const float* __restrict__ ew,
    const float* __restrict__ Wt) {
    int tid = threadIdx.x;
    if (blockIdx.x > 0) {
        int idx = (blockIdx.x - 1) * 256 + tid;   // < 49152
        int o = idx / 384, m = idx % 384;
        g_wt[m * Hv + o] = Wt[o * 384 + m];
        return;
    }

    __shared__ int   sis64;
    __shared__ float sdeg[Nv];
    __shared__ int   scnt[Nv];
    __shared__ float sdinv[Nv];
    __shared__ int   s[512];
    __shared__ int   sfill[Nv];

    if (tid == 0) {
        const long long* p = (const long long*)ei;
        int ok64 = 1;
        for (int j = 0; j < 8; ++j) {
            long long v = p[j];
            if (v < 0 || v >= Nv) ok64 = 0;
        }
        sis64 = ok64;
    }
    for (int i = tid; i < Nv; i += 256) { sdeg[i] = 0.0f; scnt[i] = 0; }
    __syncthreads();
    int is64 = sis64;

    auto lidx = [&](int i) -> int {
        long long v = is64 ? ((const long long*)ei)[i] : (long long)((const int*)ei)[i];
        if (v < 0) v = 0;
        if (v >= Nv) v = Nv - 1;
        return (int)v;
    };

    for (int e = tid; e < Ev; e += 256) {
        int dst = lidx(Ev + e);
        atomicAdd(&sdeg[dst], ew[e]);
        atomicAdd(&scnt[dst], 1);
    }
    __syncthreads();

    // dinv + counts (incl. self loop)
    int c0 = 0, c1 = 0;
    {
        int i0 = tid, i1 = tid + 256;
        if (i0 < Nv) { sdinv[i0] = rsqrtf(sdeg[i0] + 1.0f); c0 = scnt[i0] + 1; }
        if (i1 < Nv) { sdinv[i1] = rsqrtf(sdeg[i1] + 1.0f); c1 = scnt[i1] + 1; }
        s[i0] = c0;
        s[i1] = c1;
    }
    __syncthreads();
    // Hillis-Steele inclusive scan over 512 slots, 256 threads
    for (int off = 1; off < 512; off <<= 1) {
        int v0 = (tid >= off) ? s[tid - off] : 0;
        int v1 = (tid + 256 >= off) ? s[tid + 256 - off] : 0;
        __syncthreads();
        s[tid] += v0;
        s[tid + 256] += v1;
        __syncthreads();
    }
    {
        int i0 = tid, i1 = tid + 256;
        if (i0 < Nv) { g_rowptr[i0 + 1] = s[i0]; sfill[i0] = s[i0] - c0; }
        if (i1 < Nv) { g_rowptr[i1 + 1] = s[i1]; sfill[i1] = s[i1] - c1; }
        if (tid == 0) g_rowptr[0] = 0;
    }
    __syncthreads();

    for (int e = tid; e < NNZ; e += 256) {
        int src, dst; float w;
        if (e < Ev) { src = lidx(e); dst = lidx(Ev + e); w = ew[e]; }
        else        { src = dst = e - Ev; w = 1.0f; }
        float v = sdinv[src] * w * sdinv[dst];
        int pos = atomicAdd(&sfill[dst], 1);
        if (pos >= 0 && pos < NNZ)
            g_ev[pos] = make_float2(v, __int_as_float(src));
    }
}

// ---------------- K2: fused input projections (xf + res), f32x2 packed ----
__global__ __launch_bounds__(128) void k_inproj(
    const float* __restrict__ x, const float* __restrict__ Wg,
    const float* __restrict__ Wr, const float* __restrict__ br) {
    __shared__ float sx[8][64];
    int h = threadIdx.x;
    unsigned long long wp[64];
#pragma unroll
    for (int i = 0; i < 64; ++i) wp[i] = pack2(Wg[i * Hv + h], Wr[i * Hv + h]);
    float brh = br[h];
    int row0 = blockIdx.x * 128;
#pragma unroll 1
    for (int c = 0; c < 16; ++c) {
        int rbase = row0 + c * 8;
        __syncthreads();
        for (int j = h; j < 512; j += 128)
            sx[j >> 6][j & 63] = x[(rbase + (j >> 6)) * Fv + (j & 63)];
        __syncthreads();
#pragma unroll
        for (int r = 0; r < 8; ++r) {
            unsigned long long acc = 0ULL;
#pragma unroll
            for (int i = 0; i < 64; i += 4) {
                float4 xv = *(const float4*)&sx[r][i];
                fma2(acc, pack2(xv.x, xv.x), wp[i + 0]);
                fma2(acc, pack2(xv.y, xv.y), wp[i + 1]);
                fma2(acc, pack2(xv.z, xv.z), wp[i + 2]);
                fma2(acc, pack2(xv.w, xv.w), wp[i + 3]);
            }
            float ag, ar; unpack2(acc, ag, ar);
            int row = rbase + r;
            g_xf [row * Hv + h] = ag;
            g_res[row * Hv + h] = ar + brh;
        }
    }
}

// ---------------- K3: GCN aggregate + bias + gelu (R4 version) ----------------
// 16 h-channels per block, static smem 500*16*4 = 32000 B
__global__ __launch_bounds__(128) void k_gcn(const float* __restrict__ bg) {
    __shared__ float sxf[Nv * 16];
    int bt = blockIdx.x;
    int hbase = blockIdx.y * 16;
    int tid = threadIdx.x;
    const float* xsrc = g_xf + bt * (Nv * Hv);
    for (int idx = tid; idx < Nv * 16; idx += 128) {
        int n = idx >> 4, hh = idx & 15;
        sxf[idx] = xsrc[n * Hv + hbase + hh];
    }
    __syncthreads();
    int hh = tid & 15;
    int ns = tid >> 4;
    float bgv = bg[hbase + hh];
    float* dst = g_hg + bt * (Nv * Hv);
    for (int n = ns; n < Nv; n += 8) {
        int rs = g_rowptr[n], re = g_rowptr[n + 1];
        float acc = 0.0f;
        int e = rs;
        for (; e + 1 < re; e += 2) {
            float2 ev0 = g_ev[e];
            float2 ev1 = g_ev[e + 1];
            acc += ev0.x * sxf[__float_as_int(ev0.y) * 16 + hh];
            acc += ev1.x * sxf[__float_as_int(ev1.y) * 16 + hh];
        }
        if (e < re) {
            float2 ev0 = g_ev[e];
            acc += ev0.x * sxf[__float_as_int(ev0.y) * 16 + hh];
        }
        dst[n * Hv + hbase + hh] = gelu_exact(acc + bgv);
    }
}

// ---------------- K4: temporal conv(K=3) + gelu + residual + LayerNorm ----
// R4 f32x2 kernel; weights now read coalesced from transposed g_wt.
__global__ __launch_bounds__(128) void k_conv(
    const float* __restrict__ btmp,
    const float* __restrict__ lnw, const float* __restrict__ lnb,
    float* __restrict__ out) {
    // input staged as [tt=34][i=128][g=2]  (tt = t_in + 1, rows 0 and 33 are pad)
    __shared__ __align__(16) float sh[34 * 256];
    __shared__ float smu[64], srs[64];
    int o = threadIdx.x;
    int p0 = blockIdx.x * 2;
    int b0 = p0 / Nv, n0 = p0 % Nv;
    int b1 = (p0 + 1) / Nv, n1 = (p0 + 1) % Nv;

    // load input tiles (channel o of both pairs, padded in t)
#pragma unroll
    for (int g = 0; g < 2; ++g) {
        int b = g ? b1 : b0, n = g ? n1 : n0;
        sh[0 * 256 + 2 * o + g] = 0.0f;
        sh[33 * 256 + 2 * o + g] = 0.0f;
        for (int t = 0; t < 32; ++t)
            sh[(t + 1) * 256 + 2 * o + g] = g_hg[((b * Tv + t) * Nv + n) * Hv + o];
    }
    __syncthreads();

    unsigned long long acc[32];
#pragma unroll
    for (int t = 0; t < 32; ++t) acc[t] = 0ULL;

    const float* wtp = g_wt + o;             // [(it*24+j)][o], lane-coalesced
    const unsigned long long* shp = (const unsigned long long*)sh; // [tt][i] pairs
#pragma unroll 1
    for (int it = 0; it < 16; ++it) {
        float w[24];
#pragma unroll
        for (int j = 0; j < 24; ++j) w[j] = wtp[(it * 24 + j) * Hv];
#pragma unroll
        for (int ii = 0; ii < 8; ++ii) {
            int i = it * 8 + ii;
            unsigned long long w0 = pack2(w[ii * 3 + 0], w[ii * 3 + 0]);
            unsigned long long w1 = pack2(w[ii * 3 + 1], w[ii * 3 + 1]);
            unsigned long long w2 = pack2(w[ii * 3 + 2], w[ii * 3 + 2]);
            const unsigned long long* col = shp + i;   // stride 128 per tt
            unsigned long long v0 = col[0];
            unsigned long long v1 = col[128];
#pragma unroll
            for (int t = 0; t < 32; ++t) {
                unsigned long long v2 = col[(t + 2) * 128];
                fma2(acc[t], w0, v0);
                fma2(acc[t], w1, v1);
                fma2(acc[t], w2, v2);
                v0 = v1; v1 = v2;
            }
        }
    }
    __syncthreads();   // done reading input; reuse sh as y buffer [64][129]

    float btv = btmp[o];
    float* shy = sh;
#pragma unroll
    for (int t = 0; t < 32; ++t) {
        float y0, y1; unpack2(acc[t], y0, y1);
        float h0 = gelu_exact(y0 + btv);
        float h1 = gelu_exact(y1 + btv);
        h0 += g_res[((b0 * Tv + t) * Nv + n0) * Hv + o];
        h1 += g_res[((b1 * Tv + t) * Nv + n1) * Hv + o];
        shy[t * 129 + o] = h0;
        shy[(32 + t) * 129 + o] = h1;
    }
    __syncthreads();

    if (o < 64) {
        int r = o;
        float s1 = 0.0f;
#pragma unroll 8
        for (int j = 0; j < 128; ++j) s1 += shy[r * 129 + j];
        float mu = s1 * (1.0f / 128.0f);
        float s2 = 0.0f;
#pragma unroll 8
        for (int j = 0; j < 128; ++j) {
            float d = shy[r * 129 + j] - mu;
            s2 += d * d;
        }
        smu[r] = mu;
        srs[r] = 1.0f / sqrtf(s2 * (1.0f / 128.0f) + 1e-5f);
    }
    __syncthreads();

    float lw = lnw[o], lb = lnb[o];
#pragma unroll
    for (int g = 0; g < 2; ++g) {
        int b = g ? b1 : b0, n = g ? n1 : n0;
        for (int t = 0; t < 32; ++t) {
            int r = g * 32 + t;
            float v = shy[r * 129 + o];
            out[((b * Tv + t) * Nv + n) * Hv + o] = (v - smu[r]) * srs[r] * lw + lb;
        }
    }
}

// ---------------- launch ----------------
extern "C" void kernel_launch(void* const* d_in, const int* in_sizes, int n_in,
                              void* d_out, int out_size) {
    const float* x   = (const float*)d_in[0];
    const void*  ei  = d_in[1];
    const float* ew  = (const float*)d_in[2];
    const float* Wg  = (const float*)d_in[3];
    const float* bg  = (const float*)d_in[4];
    const float* Wt  = (const float*)d_in[5];
    const float* btm = (const float*)d_in[6];
    const float* lnw = (const float*)d_in[7];
    const float* lnb = (const float*)d_in[8];
    const float* Wr  = (const float*)d_in[9];
    const float* br  = (const float*)d_in[10];
    float* out = (float*)d_out;

    p_prep<<<193, 256>>>(ei, ew, Wt);
    k_inproj<<<1000, 128>>>(x, Wg, Wr, br);
    k_gcn<<<dim3(BT, 8), 128>>>(bg);
    k_conv<<<2000, 128>>>(btm, lnw, lnb, out);
}

// round 10
// speedup vs baseline: 1.2493x; 1.0583x over previous
#include <cuda_runtime.h>
#include <math.h>

#define Bv  8
#define Tv  32
#define Nv  500
#define Fv  64
#define Hv  128
#define Ev  8000
#define BT  256            // B*T
#define BTN 128000         // B*T*N
#define NNZ (Ev + Nv)

// ---------------- scratch (static device globals: allowed) ----------------
__device__ float  g_xf [BTN * Hv];   // x @ W_gcn            (bt, n, h)
__device__ float  g_res[BTN * Hv];   // x @ W_res + b_res    (bt, n, h)
__device__ float  g_hg [BTN * Hv];   // gelu(gcn agg + b)    (bt, n, h)
__device__ float  g_wt [384 * Hv];   // W_temp transposed: [(i*3+k)][o]
__device__ float  g_deg [Nv];
__device__ float  g_dinv[Nv];
__device__ int    g_cnt [Nv];
__device__ int    g_rowptr[Nv + 1];
__device__ int    g_fill[Nv];
__device__ float2 g_ev[NNZ];         // {norm, __int_as_float(src)} CSR by dst
__device__ int    g_is64;            // edge_index dtype flag

// ---------------- helpers ----------------
__device__ __forceinline__ unsigned long long pack2(float lo, float hi) {
    unsigned long long r;
    asm("mov.b64 %0, {%1, %2};" : "=l"(r) : "f"(lo), "f"(hi));
    return r;
}
__device__ __forceinline__ void unpack2(unsigned long long v, float& lo, float& hi) {
    asm("mov.b64 {%0, %1}, %2;" : "=f"(lo), "=f"(hi) : "l"(v));
}
__device__ __forceinline__ void fma2(unsigned long long& d, unsigned long long a,
                                     unsigned long long b) {
    asm("fma.rn.f32x2 %0, %1, %2, %0;" : "+l"(d) : "l"(a), "l"(b));
}
__device__ __forceinline__ float gelu_exact(float x) {
    return 0.5f * x * (1.0f + erff(x * 0.7071067811865476f));
}
__device__ __forceinline__ int load_idx(const void* ei, int i) {
    long long v;
    if (g_is64) v = ((const long long*)ei)[i];
    else        v = ((const int*)ei)[i];
    if (v < 0) v = 0;
    if (v >= Nv) v = Nv - 1;
    return (int)v;
}

// ---------------- P0: dtype detect + zero counters ----------------
__global__ void p_start(const void* __restrict__ ei) {
    int i = threadIdx.x;
    if (i == 0) {
        const long long* p = (const long long*)ei;
        int ok64 = 1;
        for (int j = 0; j < 8; ++j) {
            long long v = p[j];
            if (v < 0 || v >= Nv) ok64 = 0;
        }
        g_is64 = ok64;
    }
    if (i < Nv) { g_deg[i] = 0.0f; g_cnt[i] = 0; }
}

// ---------------- P1: degree + counts; extra blocks transpose W_temp ------
__global__ void p_deg(const void* __restrict__ ei, const float* __restrict__ ew,
                      const float* __restrict__ Wt) {
    if (blockIdx.x >= 63) {
        int idx = (blockIdx.x - 63) * 128 + threadIdx.x;   // < 49152
        if (idx < 128 * 384) {
            int o = idx / 384, m = idx % 384;
            g_wt[m * Hv + o] = Wt[o * 384 + m];
        }
        return;
    }
    int e = blockIdx.x * 128 + threadIdx.x;
    if (e >= Ev) return;
    int dst = load_idx(ei, Ev + e);
    atomicAdd(&g_deg[dst], ew[e]);
    atomicAdd(&g_cnt[dst], 1);
}

// ---------------- P2: dinv + prefix scan -> rowptr/fill ----------------
__global__ void p_scan() {
    __shared__ int s[512];
    int tid = threadIdx.x;
    int c = 0;
    if (tid < Nv) {
        float d = g_deg[tid] + 1.0f;           // + self loop weight
        g_dinv[tid] = rsqrtf(d);
        c = g_cnt[tid] + 1;                    // + self loop edge
    }
    s[tid] = c;
    __syncthreads();
    for (int off = 1; off < 512; off <<= 1) {
        int v = (tid >= off) ? s[tid - off] : 0;
        __syncthreads();
        s[tid] += v;
        __syncthreads();
    }
    if (tid < Nv) {
        g_rowptr[tid + 1] = s[tid];
        g_fill[tid] = s[tid] - c;
        if (tid == 0) g_rowptr[0] = 0;
    }
}

// ---------------- P3: CSR fill with normalized edge values ----------------
__global__ void p_fill(const void* __restrict__ ei, const float* __restrict__ ew) {
    int e = blockIdx.x * blockDim.x + threadIdx.x;
    if (e >= NNZ) return;
    int src, dst; float w;
    if (e < Ev) { src = load_idx(ei, e); dst = load_idx(ei, Ev + e); w = ew[e]; }
    else        { src = dst = e - Ev; w = 1.0f; }
    float v = g_dinv[src] * w * g_dinv[dst];
    int pos = atomicAdd(&g_fill[dst], 1);
    if (pos >= 0 && pos < NNZ)
        g_ev[pos] = make_float2(v, __int_as_float(src));
}

// ---------------- K2: fused input projections (xf + res), f32x2 packed ----
__global__ __launch_bounds__(128) void k_inproj(
    const float* __restrict__ x, const float* __restrict__ Wg,
    const float* __restrict__ Wr, const float* __restrict__ br) {
    __shared__ float sx[8][64];
    int h = threadIdx.x;
    unsigned long long wp[64];
#pragma unroll
    for (int i = 0; i < 64; ++i) wp[i] = pack2(Wg[i * Hv + h], Wr[i * Hv + h]);
    float brh = br[h];
    int row0 = blockIdx.x * 128;
#pragma unroll 1
    for (int c = 0; c < 16; ++c) {
        int rbase = row0 + c * 8;
        __syncthreads();
        for (int j = h; j < 512; j += 128)
            sx[j >> 6][j & 63] = x[(rbase + (j >> 6)) * Fv + (j & 63)];
        __syncthreads();
#pragma unroll
        for (int r = 0; r < 8; ++r) {
            unsigned long long acc = 0ULL;
#pragma unroll
            for (int i = 0; i < 64; i += 4) {
                float4 xv = *(const float4*)&sx[r][i];
                fma2(acc, pack2(xv.x, xv.x), wp[i + 0]);
                fma2(acc, pack2(xv.y, xv.y), wp[i + 1]);
                fma2(acc, pack2(xv.z, xv.z), wp[i + 2]);
                fma2(acc, pack2(xv.w, xv.w), wp[i + 3]);
            }
            float ag, ar; unpack2(acc, ag, ar);
            int row = rbase + r;
            g_xf [row * Hv + h] = ag;
            g_res[row * Hv + h] = ar + brh;
        }
    }
}

// ---------------- K3: GCN aggregate + bias + gelu (R4 version) ------------
__global__ __launch_bounds__(128) void k_gcn(const float* __restrict__ bg) {
    __shared__ float sxf[Nv * 16];
    int bt = blockIdx.x;
    int hbase = blockIdx.y * 16;
    int tid = threadIdx.x;
    const float* xsrc = g_xf + bt * (Nv * Hv);
    for (int idx = tid; idx < Nv * 16; idx += 128) {
        int n = idx >> 4, hh = idx & 15;
        sxf[idx] = xsrc[n * Hv + hbase + hh];
    }
    __syncthreads();
    int hh = tid & 15;
    int ns = tid >> 4;
    float bgv = bg[hbase + hh];
    float* dst = g_hg + bt * (Nv * Hv);
    for (int n = ns; n < Nv; n += 8) {
        int rs = g_rowptr[n], re = g_rowptr[n + 1];
        float acc = 0.0f;
        int e = rs;
        for (; e + 1 < re; e += 2) {
            float2 ev0 = g_ev[e];
            float2 ev1 = g_ev[e + 1];
            acc += ev0.x * sxf[__float_as_int(ev0.y) * 16 + hh];
            acc += ev1.x * sxf[__float_as_int(ev1.y) * 16 + hh];
        }
        if (e < re) {
            float2 ev0 = g_ev[e];
            acc += ev0.x * sxf[__float_as_int(ev0.y) * 16 + hh];
        }
        dst[n * Hv + hbase + hh] = gelu_exact(acc + bgv);
    }
}

// ---------------- K4: temporal conv(K=3) + gelu + residual + LayerNorm ----
// v3: LDS.128 double-column (1 LDS : 6 FFMA2), per-ii weight loads (low regs),
// coalesced transposed weights, target 5+ CTAs/SM.
__global__ __launch_bounds__(128, 5) void k_conv(
    const float* __restrict__ btmp,
    const float* __restrict__ lnw, const float* __restrict__ lnb,
    float* __restrict__ out) {
    // input staged as [tt=34][i=128][g=2]  (tt = t_in + 1, rows 0 and 33 are pad)
    __shared__ __align__(16) float sh[34 * 256];
    __shared__ float smu[64], srs[64];
    int o = threadIdx.x;
    int p0 = blockIdx.x * 2;
    int b0 = p0 / Nv, n0 = p0 % Nv;
    int b1 = (p0 + 1) / Nv, n1 = (p0 + 1) % Nv;

    // load input tiles (channel o of both pairs, padded in t)
#pragma unroll
    for (int g = 0; g < 2; ++g) {
        int b = g ? b1 : b0, n = g ? n1 : n0;
        sh[0 * 256 + 2 * o + g] = 0.0f;
        sh[33 * 256 + 2 * o + g] = 0.0f;
        for (int t = 0; t < 32; ++t)
            sh[(t + 1) * 256 + 2 * o + g] = g_hg[((b * Tv + t) * Nv + n) * Hv + o];
    }
    __syncthreads();

    unsigned long long acc[32];
#pragma unroll
    for (int t = 0; t < 32; ++t) acc[t] = 0ULL;

    const float* wtp = g_wt + o;           // [(m)][o], lane-coalesced
    const ulonglong2* colbase = (const ulonglong2*)sh;  // [tt][64] pair-of-pairs
#pragma unroll 1
    for (int q = 0; q < 64; ++q) {         // q = it*4 + ii/2 ; i = 2q
        int m = q * 6;                     // weight row base: i*3 = 6q
        float wa0 = wtp[(m + 0) * Hv];
        float wa1 = wtp[(m + 1) * Hv];
        float wa2 = wtp[(m + 2) * Hv];
        float wb0 = wtp[(m + 3) * Hv];
        float wb1 = wtp[(m + 4) * Hv];
        float wb2 = wtp[(m + 5) * Hv];
        unsigned long long w0a = pack2(wa0, wa0), w1a = pack2(wa1, wa1),
                           w2a = pack2(wa2, wa2);
        unsigned long long w0b = pack2(wb0, wb0), w1b = pack2(wb1, wb1),
                           w2b = pack2(wb2, wb2);
        const ulonglong2* col = colbase + q;   // stride 64 per tt
        ulonglong2 v0 = col[0];
        ulonglong2 v1 = col[64];
#pragma unroll
        for (int t = 0; t < 32; ++t) {
            ulonglong2 v2 = col[(t + 2) * 64];
            fma2(acc[t], w0a, v0.x);
            fma2(acc[t], w0b, v0.y);
            fma2(acc[t], w1a, v1.x);
            fma2(acc[t], w1b, v1.y);
            fma2(acc[t], w2a, v2.x);
            fma2(acc[t], w2b, v2.y);
            v0 = v1; v1 = v2;
        }
    }
    __syncthreads();   // done reading input; reuse sh as y buffer [64][129]

    float btv = btmp[o];
    float* shy = sh;
#pragma unroll
    for (int t = 0; t < 32; ++t) {
        float y0, y1; unpack2(acc[t], y0, y1);
        float h0 = gelu_exact(y0 + btv);
        float h1 = gelu_exact(y1 + btv);
        h0 += g_res[((b0 * Tv + t) * Nv + n0) * Hv + o];
        h1 += g_res[((b1 * Tv + t) * Nv + n1) * Hv + o];
        shy[t * 129 + o] = h0;
        shy[(32 + t) * 129 + o] = h1;
    }
    __syncthreads();

    if (o < 64) {
        int r = o;
        float s1 = 0.0f;
#pragma unroll 8
        for (int j = 0; j < 128; ++j) s1 += shy[r * 129 + j];
        float mu = s1 * (1.0f / 128.0f);
        float s2 = 0.0f;
#pragma unroll 8
        for (int j = 0; j < 128; ++j) {
            float d = shy[r * 129 + j] - mu;
            s2 += d * d;
        }
        smu[r] = mu;
        srs[r] = rsqrtf(s2 * (1.0f / 128.0f) + 1e-5f);
    }
    __syncthreads();

    float lw = lnw[o], lb = lnb[o];
#pragma unroll
    for (int g = 0; g < 2; ++g) {
        int b = g ? b1 : b0, n = g ? n1 : n0;
        for (int t = 0; t < 32; ++t) {
            int r = g * 32 + t;
            float v = shy[r * 129 + o];
            out[((b * Tv + t) * Nv + n) * Hv + o] = (v - smu[r]) * srs[r] * lw + lb;
        }
    }
}

// ---------------- launch ----------------
extern "C" void kernel_launch(void* const* d_in, const int* in_sizes, int n_in,
                              void* d_out, int out_size) {
    const float* x   = (const float*)d_in[0];
    const void*  ei  = d_in[1];
    const float* ew  = (const float*)d_in[2];
    const float* Wg  = (const float*)d_in[3];
    const float* bg  = (const float*)d_in[4];
    const float* Wt  = (const float*)d_in[5];
    const float* btm = (const float*)d_in[6];
    const float* lnw = (const float*)d_in[7];
    const float* lnb = (const float*)d_in[8];
    const float* Wr  = (const float*)d_in[9];
    const float* br  = (const float*)d_in[10];
    float* out = (float*)d_out;

    p_start<<<1, 512>>>(ei);
    p_deg <<<63 + 384, 128>>>(ei, ew, Wt);
    p_scan<<<1, 512>>>();
    p_fill<<<(NNZ + 127) / 128, 128>>>(ei, ew);
    k_inproj<<<1000, 128>>>(x, Wg, Wr, br);
    k_gcn<<<dim3(BT, 8), 128>>>(bg);
    k_conv<<<2000, 128>>>(btm, lnw, lnb, out);
}

// round 11
// speedup vs baseline: 1.2773x; 1.0224x over previous
#include <cuda_runtime.h>
#include <math.h>

#define Bv  8
#define Tv  32
#define Nv  500
#define Fv  64
#define Hv  128
#define Ev  8000
#define BT  256            // B*T
#define BTN 128000         // B*T*N
#define NNZ (Ev + Nv)

// ---------------- scratch (static device globals: allowed) ----------------
__device__ float  g_xf [BTN * Hv];   // x @ W_gcn            (bt, n, h)
__device__ float  g_res[BTN * Hv];   // x @ W_res + b_res    (bt, n, h)
__device__ float  g_hg [BTN * Hv];   // gelu(gcn agg + b)    (bt, n, h)
__device__ float  g_wt [384 * Hv];   // W_temp transposed: [(i*3+k)][o]
__device__ float  g_deg [Nv];
__device__ float  g_dinv[Nv];
__device__ int    g_cnt [Nv];
__device__ int    g_rowptr[Nv + 1];
__device__ int    g_fill[Nv];
__device__ float2 g_ev[NNZ];         // {norm, __int_as_float(src)} CSR by dst
__device__ int    g_is64;            // edge_index dtype flag

// ---------------- helpers ----------------
__device__ __forceinline__ unsigned long long pack2(float lo, float hi) {
    unsigned long long r;
    asm("mov.b64 %0, {%1, %2};" : "=l"(r) : "f"(lo), "f"(hi));
    return r;
}
__device__ __forceinline__ void unpack2(unsigned long long v, float& lo, float& hi) {
    asm("mov.b64 {%0, %1}, %2;" : "=f"(lo), "=f"(hi) : "l"(v));
}
__device__ __forceinline__ void fma2(unsigned long long& d, unsigned long long a,
                                     unsigned long long b) {
    asm("fma.rn.f32x2 %0, %1, %2, %0;" : "+l"(d) : "l"(a), "l"(b));
}
__device__ __forceinline__ float gelu_exact(float x) {
    return 0.5f * x * (1.0f + erff(x * 0.7071067811865476f));
}
__device__ __forceinline__ int load_idx(const void* ei, int i) {
    long long v;
    if (g_is64) v = ((const long long*)ei)[i];
    else        v = ((const int*)ei)[i];
    if (v < 0) v = 0;
    if (v >= Nv) v = Nv - 1;
    return (int)v;
}

// ---------------- P0: dtype detect + zero counters ----------------
__global__ void p_start(const void* __restrict__ ei) {
    int i = threadIdx.x;
    if (i == 0) {
        const long long* p = (const long long*)ei;
        int ok64 = 1;
        for (int j = 0; j < 8; ++j) {
            long long v = p[j];
            if (v < 0 || v >= Nv) ok64 = 0;
        }
        g_is64 = ok64;
    }
    if (i < Nv) { g_deg[i] = 0.0f; g_cnt[i] = 0; }
}

// ---------------- P1: degree + counts; extra blocks transpose W_temp ------
__global__ void p_deg(const void* __restrict__ ei, const float* __restrict__ ew,
                      const float* __restrict__ Wt) {
    if (blockIdx.x >= 63) {
        int idx = (blockIdx.x - 63) * 128 + threadIdx.x;   // < 49152
        if (idx < 128 * 384) {
            int o = idx / 384, m = idx % 384;
            g_wt[m * Hv + o] = Wt[o * 384 + m];
        }
        return;
    }
    int e = blockIdx.x * 128 + threadIdx.x;
    if (e >= Ev) return;
    int dst = load_idx(ei, Ev + e);
    atomicAdd(&g_deg[dst], ew[e]);
    atomicAdd(&g_cnt[dst], 1);
}

// ---------------- P2: dinv + prefix scan -> rowptr/fill ----------------
__global__ void p_scan() {
    __shared__ int s[512];
    int tid = threadIdx.x;
    int c = 0;
    if (tid < Nv) {
        float d = g_deg[tid] + 1.0f;           // + self loop weight
        g_dinv[tid] = rsqrtf(d);
        c = g_cnt[tid] + 1;                    // + self loop edge
    }
    s[tid] = c;
    __syncthreads();
    for (int off = 1; off < 512; off <<= 1) {
        int v = (tid >= off) ? s[tid - off] : 0;
        __syncthreads();
        s[tid] += v;
        __syncthreads();
    }
    if (tid < Nv) {
        g_rowptr[tid + 1] = s[tid];
        g_fill[tid] = s[tid] - c;
        if (tid == 0) g_rowptr[0] = 0;
    }
}

// ---------------- P3: CSR fill with normalized edge values ----------------
__global__ void p_fill(const void* __restrict__ ei, const float* __restrict__ ew) {
    int e = blockIdx.x * blockDim.x + threadIdx.x;
    if (e >= NNZ) return;
    int src, dst; float w;
    if (e < Ev) { src = load_idx(ei, e); dst = load_idx(ei, Ev + e); w = ew[e]; }
    else        { src = dst = e - Ev; w = 1.0f; }
    float v = g_dinv[src] * w * g_dinv[dst];
    int pos = atomicAdd(&g_fill[dst], 1);
    if (pos >= 0 && pos < NNZ)
        g_ev[pos] = make_float2(v, __int_as_float(src));
}

// ---------------- K2: fused input projections (xf + res), f32x2 packed ----
__global__ __launch_bounds__(128) void k_inproj(
    const float* __restrict__ x, const float* __restrict__ Wg,
    const float* __restrict__ Wr, const float* __restrict__ br) {
    __shared__ float sx[8][64];
    int h = threadIdx.x;
    unsigned long long wp[64];
#pragma unroll
    for (int i = 0; i < 64; ++i) wp[i] = pack2(Wg[i * Hv + h], Wr[i * Hv + h]);
    float brh = br[h];
    int row0 = blockIdx.x * 128;
#pragma unroll 1
    for (int c = 0; c < 16; ++c) {
        int rbase = row0 + c * 8;
        __syncthreads();
        for (int j = h; j < 512; j += 128)
            sx[j >> 6][j & 63] = x[(rbase + (j >> 6)) * Fv + (j & 63)];
        __syncthreads();
#pragma unroll
        for (int r = 0; r < 8; ++r) {
            unsigned long long acc = 0ULL;
#pragma unroll
            for (int i = 0; i < 64; i += 4) {
                float4 xv = *(const float4*)&sx[r][i];
                fma2(acc, pack2(xv.x, xv.x), wp[i + 0]);
                fma2(acc, pack2(xv.y, xv.y), wp[i + 1]);
                fma2(acc, pack2(xv.z, xv.z), wp[i + 2]);
                fma2(acc, pack2(xv.w, xv.w), wp[i + 3]);
            }
            float ag, ar; unpack2(acc, ag, ar);
            int row = rbase + r;
            g_xf [row * Hv + h] = ag;
            g_res[row * Hv + h] = ar + brh;
        }
    }
}

// ---------------- K3: GCN aggregate + bias + gelu (R4 version) ------------
__global__ __launch_bounds__(128) void k_gcn(const float* __restrict__ bg) {
    __shared__ float sxf[Nv * 16];
    int bt = blockIdx.x;
    int hbase = blockIdx.y * 16;
    int tid = threadIdx.x;
    const float* xsrc = g_xf + bt * (Nv * Hv);
    for (int idx = tid; idx < Nv * 16; idx += 128) {
        int n = idx >> 4, hh = idx & 15;
        sxf[idx] = xsrc[n * Hv + hbase + hh];
    }
    __syncthreads();
    int hh = tid & 15;
    int ns = tid >> 4;
    float bgv = bg[hbase + hh];
    float* dst = g_hg + bt * (Nv * Hv);
    for (int n = ns; n < Nv; n += 8) {
        int rs = g_rowptr[n], re = g_rowptr[n + 1];
        float acc = 0.0f;
        int e = rs;
        for (; e + 1 < re; e += 2) {
            float2 ev0 = g_ev[e];
            float2 ev1 = g_ev[e + 1];
            acc += ev0.x * sxf[__float_as_int(ev0.y) * 16 + hh];
            acc += ev1.x * sxf[__float_as_int(ev1.y) * 16 + hh];
        }
        if (e < re) {
            float2 ev0 = g_ev[e];
            acc += ev0.x * sxf[__float_as_int(ev0.y) * 16 + hh];
        }
        dst[n * Hv + hbase + hh] = gelu_exact(acc + bgv);
    }
}

// ---------------- K4: temporal conv(K=3) + gelu + residual + LayerNorm ----
// v4: ONE (b,n) per block; t-dimension packed into f32x2 lanes (t, t+16).
// acc = 16 ulonglong (32 regs). p[s][i] = (x[s-1], x[s+15]) broadcast LDS.128.
__global__ __launch_bounds__(128) void k_conv(
    const float* __restrict__ btmp,
    const float* __restrict__ lnw, const float* __restrict__ lnb,
    float* __restrict__ out) {
    // buffer reused: phase 1 = p[s=18][i=128] float2 (18432 B)
    //                phase 2 = y[32][129] float (16512 B)
    __shared__ __align__(16) char smbuf[18432];
    __shared__ float smu[32], srs[32];
    int o = threadIdx.x;
    int bn = blockIdx.x;
    int b = bn / Nv, n = bn % Nv;

    // ---- stage packed input pairs ----
    {
        float xv[32];
        const float* src = g_hg + ((size_t)(b * Tv) * Nv + n) * Hv + o;
#pragma unroll
        for (int t = 0; t < 32; ++t) xv[t] = src[(size_t)t * Nv * Hv];
        float2* sp = (float2*)smbuf;          // [s][128]
#pragma unroll
        for (int s = 0; s < 18; ++s) {
            float lo = (s == 0)  ? 0.0f : xv[s - 1];
            float hi = (s == 17) ? 0.0f : xv[s + 15];
            sp[s * 128 + o] = make_float2(lo, hi);
        }
    }
    __syncthreads();

    unsigned long long acc[16];
#pragma unroll
    for (int t = 0; t < 16; ++t) acc[t] = 0ULL;

    const float* wtp = g_wt + o;               // [(m)][o], lane-coalesced
    const ulonglong2* colbase = (const ulonglong2*)smbuf;   // [s][64]
#pragma unroll 1
    for (int q = 0; q < 64; ++q) {             // i = 2q, 2q+1
        int m = q * 6;
        float wa0 = wtp[(m + 0) * Hv];
        float wa1 = wtp[(m + 1) * Hv];
        float wa2 = wtp[(m + 2) * Hv];
        float wb0 = wtp[(m + 3) * Hv];
        float wb1 = wtp[(m + 4) * Hv];
        float wb2 = wtp[(m + 5) * Hv];
        unsigned long long w0a = pack2(wa0, wa0), w1a = pack2(wa1, wa1),
                           w2a = pack2(wa2, wa2);
        unsigned long long w0b = pack2(wb0, wb0), w1b = pack2(wb1, wb1),
                           w2b = pack2(wb2, wb2);
        const ulonglong2* col = colbase + q;    // stride 64 per s
        ulonglong2 v0 = col[0];                 // s = t + kk
        ulonglong2 v1 = col[64];
#pragma unroll
        for (int t = 0; t < 16; ++t) {
            ulonglong2 v2 = col[(t + 2) * 64];
            fma2(acc[t], w0a, v0.x);
            fma2(acc[t], w0b, v0.y);
            fma2(acc[t], w1a, v1.x);
            fma2(acc[t], w1b, v1.y);
            fma2(acc[t], w2a, v2.x);
            fma2(acc[t], w2b, v2.y);
            v0 = v1; v1 = v2;
        }
    }
    __syncthreads();   // done reading p; reuse smbuf as y[32][129]

    float btv = btmp[o];
    float* shy = (float*)smbuf;
    {
        const float* resp = g_res + ((size_t)(b * Tv) * Nv + n) * Hv + o;
#pragma unroll
        for (int t = 0; t < 16; ++t) {
            float y0, y1; unpack2(acc[t], y0, y1);
            float h0 = gelu_exact(y0 + btv) + resp[(size_t)t * Nv * Hv];
            float h1 = gelu_exact(y1 + btv) + resp[(size_t)(t + 16) * Nv * Hv];
            shy[t * 129 + o] = h0;
            shy[(t + 16) * 129 + o] = h1;
        }
    }
    __syncthreads();

    if (o < 32) {
        int r = o;
        float s1 = 0.0f;
#pragma unroll 8
        for (int j = 0; j < 128; ++j) s1 += shy[r * 129 + j];
        float mu = s1 * (1.0f / 128.0f);
        float s2 = 0.0f;
#pragma unroll 8
        for (int j = 0; j < 128; ++j) {
            float d = shy[r * 129 + j] - mu;
            s2 += d * d;
        }
        smu[r] = mu;
        srs[r] = rsqrtf(s2 * (1.0f / 128.0f) + 1e-5f);
    }
    __syncthreads();

    float lw = lnw[o], lb = lnb[o];
    float* op = out + ((size_t)(b * Tv) * Nv + n) * Hv + o;
#pragma unroll
    for (int t = 0; t < 32; ++t) {
        float v = shy[t * 129 + o];
        op[(size_t)t * Nv * Hv] = (v - smu[t]) * srs[t] * lw + lb;
    }
}

// ---------------- launch ----------------
extern "C" void kernel_launch(void* const* d_in, const int* in_sizes, int n_in,
                              void* d_out, int out_size) {
    const float* x   = (const float*)d_in[0];
    const void*  ei  = d_in[1];
    const float* ew  = (const float*)d_in[2];
    const float* Wg  = (const float*)d_in[3];
    const float* bg  = (const float*)d_in[4];
    const float* Wt  = (const float*)d_in[5];
    const float* btm = (const float*)d_in[6];
    const float* lnw = (const float*)d_in[7];
    const float* lnb = (const float*)d_in[8];
    const float* Wr  = (const float*)d_in[9];
    const float* br  = (const float*)d_in[10];
    float* out = (float*)d_out;

    p_start<<<1, 512>>>(ei);
    p_deg <<<63 + 384, 128>>>(ei, ew, Wt);
    p_scan<<<1, 512>>>();
    p_fill<<<(NNZ + 127) / 128, 128>>>(ei, ew);
    k_inproj<<<1000, 128>>>(x, Wg, Wr, br);
    k_gcn<<<dim3(BT, 8), 128>>>(bg);
    k_conv<<<4000, 128>>>(btm, lnw, lnb, out);
}